// round 8
// baseline (speedup 1.0000x reference)
#include <cuda_runtime.h>

// Problem constants
#define NN 2
#define RR 65536
#define KK 64
#define CC 16
#define NRAYS (NN*RR)          // 131072
#define KM1 63

// Output layout: tuple flattened in order
#define OFF_CC 0
#define OFF_RD (NRAYS*CC)              // 2,097,152
#define OFF_W  (OFF_RD + NRAYS)        // 2,228,224
#define OFF_TE (OFF_W + NRAYS*KM1)     // 10,485,760

#define RAYS_PER_BLOCK 64
#define THREADS 256

__device__ int g_min_bits;
__device__ int g_max_bits;

// ---------------------------------------------------------------------------
// Kernel 0: reset global min/max (runs every replay — graph-deterministic)
// ---------------------------------------------------------------------------
__global__ void init_minmax_kernel() {
    g_min_bits = 0x7f7fffff;   // FLT_MAX (all radii positive)
    g_max_bits = 0;            // 0.0f
}

// ---------------------------------------------------------------------------
// Kernel 1: global min/max over radii midpoints. radii sorted along K, so
// per-ray min midpoint = 0.5*(r0+r1), max = 0.5*(r62+r63).
// ---------------------------------------------------------------------------
__global__ void minmax_kernel(const float* __restrict__ radii) {
    int ray = blockIdx.x * blockDim.x + threadIdx.x;
    float mn = 3.402823466e38f;
    float mx = 0.0f;
    if (ray < NRAYS) {
        float2 lo = *(const float2*)(radii + (size_t)ray * KK);
        float2 hi = *(const float2*)(radii + (size_t)ray * KK + (KK - 2));
        mn = 0.5f * (lo.x + lo.y);
        mx = 0.5f * (hi.x + hi.y);
    }
    #pragma unroll
    for (int o = 16; o > 0; o >>= 1) {
        mn = fminf(mn, __shfl_xor_sync(0xffffffffu, mn, o));
        mx = fmaxf(mx, __shfl_xor_sync(0xffffffffu, mx, o));
    }
    __shared__ float smn[8], smx[8];
    int w = threadIdx.x >> 5, l = threadIdx.x & 31;
    if (l == 0) { smn[w] = mn; smx[w] = mx; }
    __syncthreads();
    if (threadIdx.x == 0) {
        #pragma unroll
        for (int i = 1; i < 8; i++) {
            mn = fminf(mn, smn[i]);
            mx = fmaxf(mx, smx[i]);
        }
        // positive floats: int ordering == float ordering
        atomicMin(&g_min_bits, __float_as_int(mn));
        atomicMax(&g_max_bits, __float_as_int(mx));
    }
}

// ---------------------------------------------------------------------------
// Kernel 2: main compositing. 64 rays per 256-thread block.
// Phase 1: threads 0..63 each run one ray's serial transmittance chain,
//          producing w[k] and color coefficients u[j] = w[j-1]+w[j] in smem.
// Phase 2: 4 threads per ray, float4 over channels: acc += c * u[k].
// ---------------------------------------------------------------------------
__global__ __launch_bounds__(THREADS)
void composite_kernel(const float* __restrict__ colors,
                      const float* __restrict__ densities,
                      const float* __restrict__ radii,
                      float* __restrict__ out) {
    __shared__ float s_w[RAYS_PER_BLOCK * KM1];  // [64][63] — matches out layout
    __shared__ float s_u[RAYS_PER_BLOCK * 65];   // [64][65] padded (bank-safe)

    const int tid = threadIdx.x;
    const int blk_ray0 = blockIdx.x * RAYS_PER_BLOCK;

    // ---------------- Phase 1: per-ray scalar chain (threads 0..63) --------
    if (tid < RAYS_PER_BLOCK) {
        const int ray = blk_ray0 + tid;
        const float* rp = radii     + (size_t)ray * KK;
        const float* dp = densities + (size_t)ray * KK;
        float* swp = s_w + tid * KM1;
        float* sup = s_u + tid * 65;

        float r0 = __ldg(rp);
        float d0 = __ldg(dp);
        float T = 1.0f, Tprev = 1.0f;
        float wsum = 0.0f, rsum = 0.0f, wprev = 0.0f;

        #pragma unroll 7
        for (int k = 0; k < KM1; k++) {
            float r1 = __ldg(rp + k + 1);
            float d1 = __ldg(dp + k + 1);
            float delta = r1 - r0;
            float dm = fmaxf(0.5f * (d0 + d1), 0.0f);
            float rm = 0.5f * (r0 + r1);
            float e = __expf(-delta * dm);
            float alpha = 1.0f - e;
            Tprev = T;
            float w = alpha * T;
            T = T * (1.0f - alpha + 1e-10f);
            swp[k] = w;
            sup[k] = wprev + w;               // u[k] = w[k-1] + w[k]
            wsum += w;
            rsum += w * rm;
            wprev = w; r0 = r1; d0 = d1;
        }
        sup[KM1] = wprev;                     // u[63] = w[62]

        // per-ray scalar outputs (2 warps, fully coalesced)
        float gmin = __int_as_float(g_min_bits);   // set by minmax_kernel
        float gmax = __int_as_float(g_max_bits);
        float cr = rsum / wsum;               // 0/0 -> nan, x/0 -> inf
        if (cr != cr) cr = __int_as_float(0x7f800000);   // nan -> +inf
        cr = fminf(fmaxf(cr, gmin), gmax);
        out[OFF_RD + ray] = cr;
        out[OFF_TE + ray] = Tprev;            // T_end = T[62]
    }
    __syncthreads();

    // ---------------- Phase 2: color accumulation (all 256 threads) --------
    {
        const int rr = tid >> 2;              // ray within block: 0..63
        const int c4 = (tid & 3) * 4;         // channel group: 0,4,8,12
        const size_t ray = (size_t)(blk_ray0 + rr);
        const float4* cp = (const float4*)(colors + ray * (KK * CC) + c4);
        const float* su = s_u + rr * 65;

        float4 acc = make_float4(0.0f, 0.0f, 0.0f, 0.0f);
        float u = su[0];                      // pipeline smem read 1 ahead
        #pragma unroll 8
        for (int k = 0; k < KK; k++) {
            float4 cv = __ldg(cp + k * 4);    // 16-float row stride
            float un = (k + 1 < KK) ? su[k + 1] : 0.0f;
            acc.x += cv.x * u;
            acc.y += cv.y * u;
            acc.z += cv.z * u;
            acc.w += cv.w * u;
            u = un;
        }
        float4 o = make_float4(acc.x - 1.0f, acc.y - 1.0f,
                               acc.z - 1.0f, acc.w - 1.0f);
        *(float4*)(out + OFF_CC + ray * CC + c4) = o;
    }

    // ---------------- weights: contiguous coalesced block store ------------
    {
        float* wout = out + OFF_W + (size_t)blk_ray0 * KM1;
        #pragma unroll
        for (int i = tid; i < RAYS_PER_BLOCK * KM1; i += THREADS)
            wout[i] = s_w[i];
    }
}

// ---------------------------------------------------------------------------
extern "C" void kernel_launch(void* const* d_in, const int* in_sizes, int n_in,
                              void* d_out, int out_size) {
    const float* colors    = (const float*)d_in[0];
    const float* densities = (const float*)d_in[1];
    const float* radii     = (const float*)d_in[2];
    float* out = (float*)d_out;

    init_minmax_kernel<<<1, 1>>>();
    minmax_kernel<<<(NRAYS + 255) / 256, 256>>>(radii);
    composite_kernel<<<NRAYS / RAYS_PER_BLOCK, THREADS>>>(colors, densities,
                                                          radii, out);
}

// round 9
// speedup vs baseline: 1.3178x; 1.3178x over previous
#include <cuda_runtime.h>

// Problem constants
#define NN 2
#define RR 65536
#define KK 64
#define CC 16
#define NRAYS (NN*RR)          // 131072
#define KM1 63

// Output layout: tuple flattened in order
#define OFF_CC 0
#define OFF_RD (NRAYS*CC)              // 2,097,152
#define OFF_W  (OFF_RD + NRAYS)        // 2,228,224
#define OFF_TE (OFF_W + NRAYS*KM1)     // 10,485,760

#define RPB 32                 // rays per block
#define THREADS 128
#define MAXK_THREADS 256
#define NPART (NRAYS / MAXK_THREADS)   // 512 partial maxima

// Per-block partial maxima of (r62+r63)/2. Fully overwritten every replay —
// no init kernel, no atomics, graph-deterministic.
__device__ float g_partial[NPART];

// ---------------------------------------------------------------------------
// Kernel 1: per-block max of last radii midpoint (radii sorted along K, so
// the global max midpoint is max over rays of 0.5*(r62+r63)).
// ---------------------------------------------------------------------------
__global__ void maxk_kernel(const float* __restrict__ radii) {
    int ray = blockIdx.x * blockDim.x + threadIdx.x;
    float2 hi = *(const float2*)(radii + (size_t)ray * KK + (KK - 2));
    float mx = 0.5f * (hi.x + hi.y);
    #pragma unroll
    for (int o = 16; o > 0; o >>= 1)
        mx = fmaxf(mx, __shfl_xor_sync(0xffffffffu, mx, o));
    __shared__ float smx[MAXK_THREADS / 32];
    int w = threadIdx.x >> 5;
    if ((threadIdx.x & 31) == 0) smx[w] = mx;
    __syncthreads();
    if (threadIdx.x == 0) {
        #pragma unroll
        for (int i = 1; i < MAXK_THREADS / 32; i++) mx = fmaxf(mx, smx[i]);
        g_partial[blockIdx.x] = mx;
    }
}

// ---------------------------------------------------------------------------
// Kernel 2: main compositing. 32 rays per 128-thread block.
// Stage:   coalesced float4 load of radii+densities into padded smem rows,
//          and block-local reduction of g_partial -> gmax.
// Phase 1: threads 0..31 each run one ray's serial transmittance chain,
//          writing w[k] to smem; emit radial-dist + T_end.
// Phase 2: 4 threads/ray, float4 over channels: acc += c[k]*(w[k-1]+w[k]).
// ---------------------------------------------------------------------------
__global__ __launch_bounds__(THREADS)
void composite_kernel(const float* __restrict__ colors,
                      const float* __restrict__ densities,
                      const float* __restrict__ radii,
                      float* __restrict__ out) {
    __shared__ float s_r[RPB * 65];   // padded rows: conflict-free
    __shared__ float s_d[RPB * 65];
    __shared__ float s_w[RPB * KM1];  // matches output flat layout
    __shared__ float s_mx[THREADS / 32];

    const int tid = threadIdx.x;
    const int ray0 = blockIdx.x * RPB;

    // -------- Stage radii + densities (coalesced float4), reduce partials --
    {
        const float4* rg = (const float4*)(radii     + (size_t)ray0 * KK);
        const float4* dg = (const float4*)(densities + (size_t)ray0 * KK);
        #pragma unroll
        for (int i = 0; i < (RPB * KK / 4) / THREADS; i++) {
            int q = tid + i * THREADS;        // 0..511 float4 index
            float4 rv = rg[q];
            float4 dv = dg[q];
            int rr = q >> 4;                  // ray within block
            int off = (q & 15) * 4;           // float offset within ray
            float* pr = s_r + rr * 65 + off;
            float* pd = s_d + rr * 65 + off;
            pr[0] = rv.x; pr[1] = rv.y; pr[2] = rv.z; pr[3] = rv.w;
            pd[0] = dv.x; pd[1] = dv.y; pd[2] = dv.z; pd[3] = dv.w;
        }
        // fold the 512 partial maxima (L2-resident, 2KB)
        float pm = fmaxf(fmaxf(g_partial[tid],       g_partial[tid + 128]),
                         fmaxf(g_partial[tid + 256], g_partial[tid + 384]));
        #pragma unroll
        for (int o = 16; o > 0; o >>= 1)
            pm = fmaxf(pm, __shfl_xor_sync(0xffffffffu, pm, o));
        if ((tid & 31) == 0) s_mx[tid >> 5] = pm;
    }
    __syncthreads();

    // -------- Phase 1: per-ray scalar chain (threads 0..31, smem reads) ----
    if (tid < RPB) {
        const float* sr = s_r + tid * 65;
        const float* sd = s_d + tid * 65;
        float* swp = s_w + tid * KM1;

        float r0 = sr[0], d0 = sd[0];
        float T = 1.0f, Tprev = 1.0f;
        float wsum = 0.0f, rsum = 0.0f;

        #pragma unroll 7
        for (int k = 0; k < KM1; k++) {
            float r1 = sr[k + 1];
            float d1 = sd[k + 1];
            float dm = fmaxf(0.5f * (d0 + d1), 0.0f);
            float rm = 0.5f * (r0 + r1);
            float e = __expf(-(r1 - r0) * dm);
            float alpha = 1.0f - e;
            Tprev = T;
            float w = alpha * T;
            T = T * (1.0f - alpha + 1e-10f);
            swp[k] = w;
            wsum += w;
            rsum += w * rm;
            r0 = r1; d0 = d1;
        }

        // cr is a convex combination of this ray's midpoints when wsum>0, so
        // the reference clip is a no-op except nan/inf (wsum~0) -> gmax.
        float gmax = fmaxf(fmaxf(s_mx[0], s_mx[1]), fmaxf(s_mx[2], s_mx[3]));
        int ray = ray0 + tid;
        out[OFF_RD + ray] = fminf(rsum / wsum, gmax);  // fminf(nan,x)=x
        out[OFF_TE + ray] = Tprev;                     // T_end = T[62]
    }
    __syncthreads();

    // -------- Phase 2: color accumulation (all 128 threads) ----------------
    {
        const int rr = tid >> 2;              // ray within block: 0..31
        const int c4 = (tid & 3) * 4;         // channel group: 0,4,8,12
        const size_t ray = (size_t)(ray0 + rr);
        const float4* cp = (const float4*)(colors + ray * (KK * CC) + c4);
        const float* sw = s_w + rr * KM1;

        float4 acc = make_float4(0.0f, 0.0f, 0.0f, 0.0f);
        float wprev = 0.0f;
        #pragma unroll 8
        for (int k = 0; k < KK; k++) {
            float4 cv = __ldg(cp + k * 4);    // 16-float row stride
            float wk = (k < KM1) ? sw[k] : 0.0f;
            float u = wprev + wk;             // u[k] = w[k-1] + w[k]
            acc.x += cv.x * u;
            acc.y += cv.y * u;
            acc.z += cv.z * u;
            acc.w += cv.w * u;
            wprev = wk;
        }
        float4 o = make_float4(acc.x - 1.0f, acc.y - 1.0f,
                               acc.z - 1.0f, acc.w - 1.0f);
        *(float4*)(out + OFF_CC + ray * CC + c4) = o;
    }

    // -------- weights: contiguous coalesced block store --------------------
    {
        float* wout = out + OFF_W + (size_t)ray0 * KM1;
        #pragma unroll
        for (int i = tid; i < RPB * KM1; i += THREADS)
            wout[i] = s_w[i];
    }
}

// ---------------------------------------------------------------------------
extern "C" void kernel_launch(void* const* d_in, const int* in_sizes, int n_in,
                              void* d_out, int out_size) {
    const float* colors    = (const float*)d_in[0];
    const float* densities = (const float*)d_in[1];
    const float* radii     = (const float*)d_in[2];
    float* out = (float*)d_out;

    maxk_kernel<<<NPART, MAXK_THREADS>>>(radii);
    composite_kernel<<<NRAYS / RPB, THREADS>>>(colors, densities, radii, out);
}

// round 10
// speedup vs baseline: 2.0340x; 1.5436x over previous
#include <cuda_runtime.h>

// Problem constants
#define KK 64
#define CC 16
#define NRAYS 131072           // N*R = 2*65536
#define KM1 63

// Output layout: tuple flattened in order
#define OFF_CC 0
#define OFF_RD (NRAYS*CC)              // 2,097,152
#define OFF_W  (OFF_RD + NRAYS)        // 2,228,224
#define OFF_TE (OFF_W + NRAYS*KM1)     // 10,485,760

#define MAXK_THREADS 256
#define NPART (NRAYS / MAXK_THREADS)   // 512 partial maxima

// Scratch: fully overwritten every replay — graph-deterministic, no init pass.
__device__ float g_partial[NPART];
__device__ float g_gmax;

// ---------------------------------------------------------------------------
// Kernel 1: per-block max of last radii midpoint (radii sorted along K ⇒
// global max midpoint = max over rays of 0.5*(r62+r63)).
// ---------------------------------------------------------------------------
__global__ void maxk_kernel(const float* __restrict__ radii) {
    int ray = blockIdx.x * blockDim.x + threadIdx.x;
    float2 hi = *(const float2*)(radii + (size_t)ray * KK + (KK - 2));
    float mx = 0.5f * (hi.x + hi.y);
    #pragma unroll
    for (int o = 16; o > 0; o >>= 1)
        mx = fmaxf(mx, __shfl_xor_sync(0xffffffffu, mx, o));
    __shared__ float smx[MAXK_THREADS / 32];
    if ((threadIdx.x & 31) == 0) smx[threadIdx.x >> 5] = mx;
    __syncthreads();
    if (threadIdx.x == 0) {
        #pragma unroll
        for (int i = 1; i < MAXK_THREADS / 32; i++) mx = fmaxf(mx, smx[i]);
        g_partial[blockIdx.x] = mx;
    }
}

// ---------------------------------------------------------------------------
// Kernel 2: fold 512 partials -> single scalar g_gmax.
// ---------------------------------------------------------------------------
__global__ void reduce_kernel() {
    int t = threadIdx.x;   // 128 threads
    float m = fmaxf(fmaxf(g_partial[t],       g_partial[t + 128]),
                    fmaxf(g_partial[t + 256], g_partial[t + 384]));
    #pragma unroll
    for (int o = 16; o > 0; o >>= 1)
        m = fmaxf(m, __shfl_xor_sync(0xffffffffu, m, o));
    __shared__ float smx[4];
    if ((t & 31) == 0) smx[t >> 5] = m;
    __syncthreads();
    if (t == 0)
        g_gmax = fmaxf(fmaxf(smx[0], smx[1]), fmaxf(smx[2], smx[3]));
}

// ---------------------------------------------------------------------------
// Kernel 3: main compositing — ONE WARP PER RAY, no block barriers.
// Lane L holds elements L and L+32 of the ray's r/d arrays (coalesced loads).
// T computed by warp-wide multiplicative inclusive scan of f = exp(-x)+eps.
// Colors then streamed as 8 x LDG.128 per lane with u[j]=w[j-1]+w[j] coeffs.
// ---------------------------------------------------------------------------
__global__ __launch_bounds__(256, 6)
void composite_kernel(const float* __restrict__ colors,
                      const float* __restrict__ densities,
                      const float* __restrict__ radii,
                      float* __restrict__ out) {
    __shared__ float s_u[8][64];          // per-warp u coefficients (2 KB)
    const unsigned FULL = 0xffffffffu;
    const int L = threadIdx.x & 31;
    const int wi = threadIdx.x >> 5;
    const int ray = blockIdx.x * 8 + wi;
    const size_t base = (size_t)ray * KK;

    // ---- coalesced loads: lane L gets elements L and L+32 -----------------
    float rA = __ldg(radii + base + L);
    float rB = __ldg(radii + base + 32 + L);
    float dA = __ldg(densities + base + L);
    float dB = __ldg(densities + base + 32 + L);

    // ---- neighbors for midpoints/deltas -----------------------------------
    float rA1 = __shfl_down_sync(FULL, rA, 1);
    float dA1 = __shfl_down_sync(FULL, dA, 1);
    float rB0 = __shfl_sync(FULL, rB, 0);
    float dB0 = __shfl_sync(FULL, dB, 0);
    if (L == 31) { rA1 = rB0; dA1 = dB0; }       // element 32
    float rB1 = __shfl_down_sync(FULL, rB, 1);   // lane31: self (padded out)
    float dB1 = __shfl_down_sync(FULL, dB, 1);

    // ---- per-interval quantities: k=L (A) and k=L+32 (B), k<=62 -----------
    float xA = (rA1 - rA) * fmaxf(0.5f * (dA + dA1), 0.0f);
    float xB = (rB1 - rB) * fmaxf(0.5f * (dB + dB1), 0.0f);
    float rmA = 0.5f * (rA + rA1);
    float rmB = 0.5f * (rB + rB1);
    float eA = __expf(-xA);
    float eB = (L == 31) ? 1.0f : __expf(-xB);   // k=63 pad: alpha=0
    float fA = eA + 1e-10f;
    float fB = (L == 31) ? 1.0f : (eB + 1e-10f);

    // ---- warp-wide multiplicative inclusive scan of f ----------------------
    float FA = fA;
    #pragma unroll
    for (int o = 1; o < 32; o <<= 1) {
        float t = __shfl_up_sync(FULL, FA, o);
        if (L >= o) FA *= t;
    }
    float tot = __shfl_sync(FULL, FA, 31);       // prod f[0..31]
    float FB = fB;
    #pragma unroll
    for (int o = 1; o < 32; o <<= 1) {
        float t = __shfl_up_sync(FULL, FB, o);
        if (L >= o) FB *= t;
    }
    FB *= tot;                                   // inclusive over 0..L+32

    // ---- transmittance T_k = F_{k-1} --------------------------------------
    float tA = __shfl_up_sync(FULL, FA, 1);
    float TA = (L == 0) ? 1.0f : tA;             // k = L
    float tB = __shfl_up_sync(FULL, FB, 1);
    float TB = (L == 0) ? tot : tB;              // k = L+32

    // ---- weights ----------------------------------------------------------
    float wA = (1.0f - eA) * TA;                 // k = 0..31
    float wB = (1.0f - eB) * TB;                 // k = 32..62 (lane31 -> 0)

    // weights output: row of 63 floats, two coalesced stores
    float* wout = out + OFF_W + (size_t)ray * KM1;
    wout[L] = wA;
    if (L < 31) wout[32 + L] = wB;

    // ---- u[j] = w[j-1] + w[j]  (u[0]=w0, u[63]=w62) -----------------------
    float pA = __shfl_up_sync(FULL, wA, 1);
    float uA = wA + ((L == 0) ? 0.0f : pA);
    float wA31 = __shfl_sync(FULL, wA, 31);
    float pB = __shfl_up_sync(FULL, wB, 1);
    float uB = wB + ((L == 0) ? wA31 : pB);
    s_u[wi][L] = uA;
    s_u[wi][32 + L] = uB;

    // ---- per-ray scalar outputs -------------------------------------------
    float ws = wA + wB;
    float rs = wA * rmA + wB * rmB;
    #pragma unroll
    for (int o = 16; o > 0; o >>= 1) {
        ws += __shfl_xor_sync(FULL, ws, o);
        rs += __shfl_xor_sync(FULL, rs, o);
    }
    float tend = __shfl_sync(FULL, TB, 30);      // T[62]
    if (L == 0) {
        // cr is a convex combination of this ray's midpoints when ws>0, so
        // the reference clip only matters for nan/inf (ws~0): fminf -> gmax.
        float cr = fminf(rs / ws, g_gmax);
        out[OFF_RD + ray] = cr;
        out[OFF_TE + ray] = tend;
    }
    __syncwarp();

    // ---- color streaming: 8 x LDG.128 per lane ----------------------------
    const float4* cp = (const float4*)(colors + base * CC);
    const float* su = &s_u[wi][L >> 2];          // sample k0 = L>>2 (+8i)
    float4 acc = make_float4(0.0f, 0.0f, 0.0f, 0.0f);
    #pragma unroll
    for (int i = 0; i < 8; i++) {
        float4 cv = __ldg(cp + i * 32 + L);
        float u = su[i * 8];
        acc.x += cv.x * u;
        acc.y += cv.y * u;
        acc.z += cv.z * u;
        acc.w += cv.w * u;
    }
    // reduce over the 8 sample-classes (lanes differing in bits 2..4)
    #pragma unroll
    for (int o = 4; o <= 16; o <<= 1) {
        acc.x += __shfl_xor_sync(FULL, acc.x, o);
        acc.y += __shfl_xor_sync(FULL, acc.y, o);
        acc.z += __shfl_xor_sync(FULL, acc.z, o);
        acc.w += __shfl_xor_sync(FULL, acc.w, o);
    }
    if (L < 4) {
        float4 o4 = make_float4(acc.x - 1.0f, acc.y - 1.0f,
                                acc.z - 1.0f, acc.w - 1.0f);
        *(float4*)(out + OFF_CC + (size_t)ray * CC + L * 4) = o4;
    }
}

// ---------------------------------------------------------------------------
extern "C" void kernel_launch(void* const* d_in, const int* in_sizes, int n_in,
                              void* d_out, int out_size) {
    const float* colors    = (const float*)d_in[0];
    const float* densities = (const float*)d_in[1];
    const float* radii     = (const float*)d_in[2];
    float* out = (float*)d_out;

    maxk_kernel<<<NPART, MAXK_THREADS>>>(radii);
    reduce_kernel<<<1, 128>>>();
    composite_kernel<<<NRAYS / 8, 256>>>(colors, densities, radii, out);
}